// round 14
// baseline (speedup 1.0000x reference)
#include <cuda_runtime.h>
#include <cuda_fp16.h>

// Fused PreNorm cross-attention, R14.
// - v GEMM only on tensor cores (mma.sync m16n8k16 fp16x2-split, fp32 acc),
//   warp tile 32m x 32n, B (Wv) fragments persistent in registers.
// - k path reassociated: r = Wk @ q^T (131K MACs) then dots = yn . r (fp32).
// - cp.async prefetch of raw y/x one chunk ahead.
// 512 threads, 1 CTA/SM persistent, 8 points per chunk.

#define THREADS 512
#define SCALE_F 0.17677669529663687f
typedef unsigned long long ull;

// ---- smem byte offsets ----
#define OFF_AH  0        // 32768 : yn hi fp16 [m=128][k=128], xor-swizzled
#define OFF_AL  32768    // 32768 : yn lo fp16
#define OFF_RAW 65536    // 69632 : raw stage [136 rows][128 f32] (alias: B init)
#define OFF_XNT 135168   // 4096  : xn transposed [i=128][p=8] fp32
#define OFF_Q   139264   // 4096  : q [p=8][128]
#define OFF_R   143360   // 16640 : r [(p*4+h)=32][130] fp32 (stride 130)
#define OFF_DOT 160000   // 2048  : dots/attn [(p*4+h)=32][m=16]
#define OFF_TMP 162048   // 12288 : 3 partial buffers [8][128] fp32
#define OFF_AOT 174336   // 4096  : attn-out transposed [i=128][p=8]
#define OFF_G   178432   // 512
#define OFF_B   178944   // 512
#define OFF_BOV 179456   // 512
#define SMEM_BYTES 179968

// xor-swizzled tile offset: row stride 256B (128 fp16), 16B chunks xor'd by row&7
static __device__ __forceinline__ int sw_off(int row, int k) {
    return row * 256 + ((((k >> 3) ^ (row & 7)) << 4)) + ((k & 7) << 1);
}
static __device__ __forceinline__ unsigned smem_u32(const void* p) {
    unsigned a;
    asm("{ .reg .u64 t; cvta.to.shared.u64 t, %1; cvt.u32.u64 %0, t; }"
        : "=r"(a) : "l"(p));
    return a;
}
static __device__ __forceinline__ ull pk2(float v) {
    ull r;
    unsigned b = __float_as_uint(v);
    asm("mov.b64 %0, {%1, %1};" : "=l"(r) : "r"(b));
    return r;
}
static __device__ __forceinline__ void ffma2(ull& a, ull x, ull w) {
    asm("fma.rn.f32x2 %0, %1, %2, %0;" : "+l"(a) : "l"(x), "l"(w));
}
static __device__ __forceinline__ float2 upk2(ull v) {
    unsigned lo, hi;
    asm("mov.b64 {%0, %1}, %2;" : "=r"(lo), "=r"(hi) : "l"(v));
    return make_float2(__uint_as_float(lo), __uint_as_float(hi));
}
static __device__ __forceinline__ void hsplit(float v, unsigned short& h,
                                              unsigned short& l) {
    __half hh = __float2half_rn(v);
    float hv = __half2float(hh);
    __half ll = __float2half_rn(v - hv);
    h = __half_as_ushort(hh);
    l = __half_as_ushort(ll);
}
static __device__ __forceinline__ void ldsm4(unsigned* r, unsigned addr) {
    asm volatile("ldmatrix.sync.aligned.m8n8.x4.shared.b16 {%0,%1,%2,%3}, [%4];"
                 : "=r"(r[0]), "=r"(r[1]), "=r"(r[2]), "=r"(r[3]) : "r"(addr));
}
static __device__ __forceinline__ void mma16816(float* d, const unsigned* a,
                                                const unsigned* b) {
    asm volatile(
        "mma.sync.aligned.m16n8k16.row.col.f32.f16.f16.f32 "
        "{%0,%1,%2,%3}, {%4,%5,%6,%7}, {%8,%9}, {%0,%1,%2,%3};"
        : "+f"(d[0]), "+f"(d[1]), "+f"(d[2]), "+f"(d[3])
        : "r"(a[0]), "r"(a[1]), "r"(a[2]), "r"(a[3]), "r"(b[0]), "r"(b[1]));
}
#define CP_ASYNC16(dst, src) \
    asm volatile("cp.async.cg.shared.global [%0], [%1], 16;" \
                 :: "r"(dst), "l"(src) : "memory")
#define CP_COMMIT() asm volatile("cp.async.commit_group;" ::: "memory")
#define CP_WAIT0()  asm volatile("cp.async.wait_group 0;" ::: "memory")

static __device__ __forceinline__ void prefetch_raw(unsigned sb, const float* y,
                                                    const float* x, long long pt0,
                                                    int tid) {
    const float4* ysrc = (const float4*)y + pt0 * 512;
    const float4* xsrc = (const float4*)x + pt0 * 32;
    for (int u = tid; u < 4352; u += THREADS) {
        unsigned dst = sb + OFF_RAW + (unsigned)u * 16;
        const float4* src = (u < 4096) ? (ysrc + u) : (xsrc + (u - 4096));
        CP_ASYNC16(dst, src);
    }
}

__global__ void __launch_bounds__(THREADS, 1)
ca_r14_kernel(const float* __restrict__ x,
              const float* __restrict__ y,
              const float* __restrict__ ln_g,
              const float* __restrict__ ln_b,
              const float* __restrict__ Wq,
              const float* __restrict__ Wkv,
              const float* __restrict__ Wo,
              const float* __restrict__ bo,
              float* __restrict__ out,
              int P)
{
    extern __shared__ float smf[];
    char* smb = (char*)smf;
    const unsigned sb = smem_u32(smf);

    const int tid  = threadIdx.x;
    const int warp = tid >> 5;
    const int lane = tid & 31;
    const int gid  = lane >> 2;
    const int tig  = lane & 3;
    const int jj   = tid & 127;
    const int qq   = tid >> 7;      // contraction quarter for q/out GEMM; also h for r GEMM

    float* sXNT = (float*)(smb + OFF_XNT);
    float* sQ   = (float*)(smb + OFF_Q);
    float* sR   = (float*)(smb + OFF_R);
    float* sDOT = (float*)(smb + OFF_DOT);
    float* sTMP = (float*)(smb + OFF_TMP);
    float* sAOT = (float*)(smb + OFF_AOT);
    float* sG   = (float*)(smb + OFF_G);
    float* sB   = (float*)(smb + OFF_B);
    float* sBO  = (float*)(smb + OFF_BOV);

    if (tid < 128) { sG[tid] = ln_g[tid]; sB[tid] = ln_b[tid]; sBO[tid] = bo[tid]; }

    // ---- stage Wv (= Wkv cols 128..255) as fp16 swizzled [n=128][k=128] ----
    for (int idx = tid; idx < 16384; idx += THREADS) {
        int k = idx >> 7, n = idx & 127;
        *(unsigned short*)(smb + OFF_RAW + sw_off(n, k)) =
            __half_as_ushort(__float2half_rn(Wkv[k * 256 + 128 + n]));
    }
    __syncthreads();

    // warp tiling: 4 m-quads x 4 n-quads (32m x 32n per warp)
    const int mq = warp >> 2;
    const int nq = warp & 3;            // == head
    // ldmatrix lane addressing
    const int rowA  = mq * 32 + (lane & 15);
    const int kca   = lane >> 4;
    const int swa   = rowA & 7;
    const int nrowB = nq * 32 + (lane & 7) + ((lane >> 4) & 1) * 8;
    const int kcb   = (lane >> 3) & 1;
    const int swb   = nrowB & 7;
    const unsigned saH = sb + OFF_AH + (unsigned)(rowA * 256);
    const unsigned saL = sb + OFF_AL + (unsigned)(rowA * 256);

    // ---- B (Wv) fragments persistent in registers: 64 regs ----
    unsigned breg[64];
    {
        const unsigned sbv = sb + OFF_RAW + (unsigned)(nrowB * 256);
#pragma unroll
        for (int ks = 0; ks < 8; ++ks) {
            unsigned bko = (unsigned)(((ks * 2 + kcb) ^ swb)) << 4;
            ldsm4(&breg[ks * 8],     sbv + bko);
            ldsm4(&breg[ks * 8 + 4], sbv + 4096 + bko);
        }
    }
    __syncthreads();   // B staging consumed; RAW free for prefetch

    // dots-phase thread mapping
    const int drow = tid >> 2;          // 0..127 = p*16+m
    const int dh   = tid & 3;
    const int dswz = drow & 7;
    const char* pAh = smb + OFF_AH + drow * 256;
    const char* pAl = smb + OFF_AL + drow * 256;
    const float* rrow = sR + ((drow >> 4) * 4 + dh) * 130;

    const int nch = P >> 3;
    int c = blockIdx.x;
    if (c < nch) prefetch_raw(sb, y, x, (long long)c * 8, tid);
    CP_COMMIT();

    for (; c < nch; c += gridDim.x) {
        const long long pt0 = (long long)c * 8;
        CP_WAIT0();
        __syncthreads();

        // ============ LN + pack from raw SMEM (136 rows) ============
        for (int r = warp; r < 136; r += 16) {
            float4 v4 = ((const float4*)(smb + OFF_RAW))[r * 32 + lane];
            float s  = v4.x + v4.y + v4.z + v4.w;
            float q2 = v4.x * v4.x + v4.y * v4.y + v4.z * v4.z + v4.w * v4.w;
#pragma unroll
            for (int o = 16; o > 0; o >>= 1) {
                s  += __shfl_xor_sync(0xffffffffu, s,  o);
                q2 += __shfl_xor_sync(0xffffffffu, q2, o);
            }
            float mu  = s * (1.0f / 128.0f);
            float var = q2 * (1.0f / 128.0f) - mu * mu;
            float rs  = rsqrtf(var + 1e-5f);
            int k0 = lane * 4;
            float n0 = (v4.x - mu) * rs * sG[k0]     + sB[k0];
            float n1 = (v4.y - mu) * rs * sG[k0 + 1] + sB[k0 + 1];
            float n2 = (v4.z - mu) * rs * sG[k0 + 2] + sB[k0 + 2];
            float n3 = (v4.w - mu) * rs * sG[k0 + 3] + sB[k0 + 3];
            if (r < 128) {
                unsigned short h0, l0, h1, l1, h2, l2, h3, l3;
                hsplit(n0, h0, l0); hsplit(n1, h1, l1);
                hsplit(n2, h2, l2); hsplit(n3, h3, l3);
                int boff = r * 256 + ((((k0 >> 3) ^ (r & 7)) << 4)) + ((k0 & 7) << 1);
                *(uint2*)(smb + OFF_AH + boff) =
                    make_uint2((unsigned)h0 | ((unsigned)h1 << 16),
                               (unsigned)h2 | ((unsigned)h3 << 16));
                *(uint2*)(smb + OFF_AL + boff) =
                    make_uint2((unsigned)l0 | ((unsigned)l1 << 16),
                               (unsigned)l2 | ((unsigned)l3 << 16));
            } else {
                int p = r - 128;
                sXNT[(k0)     * 8 + p] = n0;
                sXNT[(k0 + 1) * 8 + p] = n1;
                sXNT[(k0 + 2) * 8 + p] = n2;
                sXNT[(k0 + 3) * 8 + p] = n3;
            }
        }
        __syncthreads();

        // ---- issue prefetch for next chunk (overlaps everything below) ----
        {
            long long cn = (long long)c + gridDim.x;
            if (cn < nch) prefetch_raw(sb, y, x, cn * 8, tid);
            CP_COMMIT();
        }

        // ============ q GEMM: 4-way contraction split ============
        {
            ull qa0 = 0, qa1 = 0, qa2 = 0, qa3 = 0;
            const float* xt  = sXNT + (qq * 32) * 8;
            const float* wqp = Wq + (qq * 32) * 128 + jj;
#pragma unroll 8
            for (int ii = 0; ii < 32; ++ii) {
                ulonglong2 xa = *(const ulonglong2*)(xt + ii * 8);
                ulonglong2 xb = *(const ulonglong2*)(xt + ii * 8 + 4);
                ull w = pk2(wqp[ii * 128]);
                ffma2(qa0, xa.x, w); ffma2(qa1, xa.y, w);
                ffma2(qa2, xb.x, w); ffma2(qa3, xb.y, w);
            }
            float2 f0 = upk2(qa0), f1 = upk2(qa1), f2 = upk2(qa2), f3 = upk2(qa3);
            float rr[8] = { f0.x, f0.y, f1.x, f1.y, f2.x, f2.y, f3.x, f3.y };
            if (qq) {
                float* tp = sTMP + (qq - 1) * 1024;
#pragma unroll
                for (int p = 0; p < 8; ++p) tp[p * 128 + jj] = rr[p];
            }
            __syncthreads();
            if (!qq) {
#pragma unroll
                for (int p = 0; p < 8; ++p)
                    sQ[p * 128 + jj] = rr[p] + sTMP[p * 128 + jj]
                                     + sTMP[1024 + p * 128 + jj]
                                     + sTMP[2048 + p * 128 + jj];
            }
            __syncthreads();
        }

        // ============ r GEMM: r[(p,h), i] = sum_d Wk[i, h*32+d] q[p,h,d] =====
        {
            const int ri = tid & 127;       // i
            const int rh = qq;              // h
            float4 wk[8];
            const float4* wkp = (const float4*)(Wkv + ri * 256 + rh * 32);
#pragma unroll
            for (int d4 = 0; d4 < 8; ++d4) wk[d4] = wkp[d4];
#pragma unroll
            for (int p = 0; p < 8; ++p) {
                const float4* qp = (const float4*)(sQ + p * 128 + rh * 32);
                float a = 0.0f;
#pragma unroll
                for (int d4 = 0; d4 < 8; ++d4) {
                    float4 qv = qp[d4];
                    a += wk[d4].x * qv.x + wk[d4].y * qv.y
                       + wk[d4].z * qv.z + wk[d4].w * qv.w;
                }
                sR[(p * 4 + rh) * 130 + ri] = a;
            }
        }
        __syncthreads();

        // ============ dots: dots[p,h,m] = yn[row] . r[(p,h)]  (fp32) ========
        {
            float dsum = 0.0f;
#pragma unroll 4
            for (int ch = 0; ch < 16; ++ch) {
                int off = (ch ^ dswz) << 4;
                uint4 ha = *(const uint4*)(pAh + off);
                uint4 la = *(const uint4*)(pAl + off);
                const float2* rp = (const float2*)(rrow + ch * 8);
                float2 fh, fl, rv;
                fh = __half22float2(*(__half2*)&ha.x);
                fl = __half22float2(*(__half2*)&la.x);
                rv = rp[0];
                dsum += (fh.x + fl.x) * rv.x + (fh.y + fl.y) * rv.y;
                fh = __half22float2(*(__half2*)&ha.y);
                fl = __half22float2(*(__half2*)&la.y);
                rv = rp[1];
                dsum += (fh.x + fl.x) * rv.x + (fh.y + fl.y) * rv.y;
                fh = __half22float2(*(__half2*)&ha.z);
                fl = __half22float2(*(__half2*)&la.z);
                rv = rp[2];
                dsum += (fh.x + fl.x) * rv.x + (fh.y + fl.y) * rv.y;
                fh = __half22float2(*(__half2*)&ha.w);
                fl = __half22float2(*(__half2*)&la.w);
                rv = rp[3];
                dsum += (fh.x + fl.x) * rv.x + (fh.y + fl.y) * rv.y;
            }
            sDOT[((drow >> 4) * 4 + dh) * 16 + (drow & 15)] = dsum * SCALE_F;
        }
        __syncthreads();

        // ============ softmax over m=16 (32 (p,h) rows) ============
        if (tid < 32) {
            float* dd = sDOT + tid * 16;
            float mx = dd[0];
#pragma unroll
            for (int m = 1; m < 16; ++m) mx = fmaxf(mx, dd[m]);
            float se = 0.0f;
            float ee[16];
#pragma unroll
            for (int m = 0; m < 16; ++m) { ee[m] = __expf(dd[m] - mx); se += ee[m]; }
            float inv = 1.0f / se;
#pragma unroll
            for (int m = 0; m < 16; ++m) dd[m] = ee[m] * inv;
        }
        __syncthreads();

        // ============ v MMA: 32m x 32n per warp, 2 fp16 terms ============
        float acc[2][4][4];
#pragma unroll
        for (int mt = 0; mt < 2; ++mt)
#pragma unroll
            for (int nt = 0; nt < 4; ++nt)
#pragma unroll
                for (int e = 0; e < 4; ++e) acc[mt][nt][e] = 0.0f;
#pragma unroll 1
        for (int t = 0; t < 2; ++t) {
            const unsigned sa = t ? saL : saH;
#pragma unroll
            for (int ks = 0; ks < 8; ++ks) {
                unsigned ako = (unsigned)(((ks * 2 + kca) ^ swa)) << 4;
#pragma unroll
                for (int mt = 0; mt < 2; ++mt) {
                    unsigned af[4];
                    ldsm4(af, sa + mt * 4096 + ako);
                    mma16816(acc[mt][0], af, &breg[ks * 8]);
                    mma16816(acc[mt][1], af, &breg[ks * 8 + 2]);
                    mma16816(acc[mt][2], af, &breg[ks * 8 + 4]);
                    mma16816(acc[mt][3], af, &breg[ks * 8 + 6]);
                }
            }
        }

        // ============ attn * v from fragments (all 16 warps) ============
#pragma unroll
        for (int mt = 0; mt < 2; ++mt) {
            int p = mq * 2 + mt;
            float ag  = sDOT[(p * 4 + nq) * 16 + gid];
            float ag8 = sDOT[(p * 4 + nq) * 16 + gid + 8];
#pragma unroll
            for (int nt = 0; nt < 4; ++nt) {
                const float* cc = acc[mt][nt];
                float o0 = ag * cc[0] + ag8 * cc[2];
                float o1 = ag * cc[1] + ag8 * cc[3];
#pragma unroll
                for (int o = 4; o < 32; o <<= 1) {
                    o0 += __shfl_xor_sync(0xffffffffu, o0, o);
                    o1 += __shfl_xor_sync(0xffffffffu, o1, o);
                }
                if (gid == 0) {
                    int d0 = nt * 8 + tig * 2;
                    sAOT[(nq * 32 + d0) * 8 + p]     = o0;
                    sAOT[(nq * 32 + d0 + 1) * 8 + p] = o1;
                }
            }
        }
        __syncthreads();

        // ============ out GEMM (4-way split) + bias + residual ============
        {
            ull oa0 = 0, oa1 = 0, oa2 = 0, oa3 = 0;
            const float* at  = sAOT + (qq * 32) * 8;
            const float* wop = Wo + (qq * 32) * 128 + jj;
#pragma unroll 8
            for (int ii = 0; ii < 32; ++ii) {
                ulonglong2 xa = *(const ulonglong2*)(at + ii * 8);
                ulonglong2 xb = *(const ulonglong2*)(at + ii * 8 + 4);
                ull w = pk2(wop[ii * 128]);
                ffma2(oa0, xa.x, w); ffma2(oa1, xa.y, w);
                ffma2(oa2, xb.x, w); ffma2(oa3, xb.y, w);
            }
            float2 f0 = upk2(oa0), f1 = upk2(oa1), f2 = upk2(oa2), f3 = upk2(oa3);
            float rr[8] = { f0.x, f0.y, f1.x, f1.y, f2.x, f2.y, f3.x, f3.y };
            if (qq) {
                float* tp = sTMP + (qq - 1) * 1024;
#pragma unroll
                for (int p = 0; p < 8; ++p) tp[p * 128 + jj] = rr[p];
            }
            __syncthreads();
            if (!qq) {
#pragma unroll
                for (int p = 0; p < 8; ++p) {
                    float v = rr[p] + sTMP[p * 128 + jj]
                            + sTMP[1024 + p * 128 + jj]
                            + sTMP[2048 + p * 128 + jj]
                            + sBO[jj] + x[(pt0 + p) * 128 + jj];
                    out[(pt0 + p) * 128 + jj] = v;
                }
            }
            __syncthreads();
        }
    }
}

extern "C" void kernel_launch(void* const* d_in, const int* in_sizes, int n_in,
                              void* d_out, int out_size) {
    const float* x    = (const float*)d_in[0];
    const float* y    = (const float*)d_in[1];
    const float* ln_g = (const float*)d_in[2];
    const float* ln_b = (const float*)d_in[3];
    const float* Wq   = (const float*)d_in[4];
    const float* Wkv  = (const float*)d_in[5];
    const float* Wo   = (const float*)d_in[6];
    const float* bo   = (const float*)d_in[7];
    float* out = (float*)d_out;

    const int P = in_sizes[0] / 128;

    int dev = 0;
    cudaGetDevice(&dev);
    int sms = 0;
    cudaDeviceGetAttribute(&sms, cudaDevAttrMultiProcessorCount, dev);
    if (sms <= 0) sms = 148;

    cudaFuncSetAttribute(ca_r14_kernel,
                         cudaFuncAttributeMaxDynamicSharedMemorySize, SMEM_BYTES);

    ca_r14_kernel<<<sms, THREADS, SMEM_BYTES>>>(
        x, y, ln_g, ln_b, Wq, Wkv, Wo, bo, out, P);
}

// round 15
// speedup vs baseline: 1.1569x; 1.1569x over previous
#include <cuda_runtime.h>
#include <cuda_fp16.h>

// Fused PreNorm cross-attention, R15 = R13 (fused k+v HMMA) + cp.async
// prefetch + B-ldsm hoisted out of the split-term loop.
// 512 threads / 16 warps, 1 CTA/SM persistent, 8 points per chunk.
// kv GEMM D[128m x 256n] = yn @ Wkv, fp16 2-term split (A=Ah+Al exact,
// B=fp16(Wkv)). Warp tile 64m x 32n. Epilogue from MMA fragments.

#define THREADS 512
#define SCALE_F 0.17677669529663687f
typedef unsigned long long ull;

// ---- smem byte offsets ----
#define OFF_BH  0        // 65536 : Wkv fp16 [n=256][k=128], xor-swizzled
#define OFF_AH  65536    // 32768 : yn hi fp16 [m=128][k=128], xor-swizzled
#define OFF_AL  98304    // 32768 : yn lo fp16
#define OFF_RAW 131072   // 69632 : raw stage [136 rows][128 f32]
#define OFF_XNT 200704   // 4096  : xn transposed [i=128][p=8] fp32
#define OFF_Q   204800   // 4096  : q [p=8][128]
#define OFF_DOT 208896   // 2048  : dots/attn [(p*4+h)=32][m=16]
#define OFF_TMP 210944   // 12288 : 3 partial buffers [8][128] fp32
#define OFF_AOT 223232   // 4096  : attn-out transposed [i=128][p=8]
#define OFF_G   227328   // 512
#define OFF_B   227840   // 512
#define OFF_BOV 228352   // 512
#define SMEM_BYTES 228864

// xor-swizzled tile offset: row stride 256B (128 fp16), 16B chunks xor'd by row&7
static __device__ __forceinline__ int sw_off(int row, int k) {
    return row * 256 + ((((k >> 3) ^ (row & 7)) << 4)) + ((k & 7) << 1);
}
static __device__ __forceinline__ unsigned smem_u32(const void* p) {
    unsigned a;
    asm("{ .reg .u64 t; cvta.to.shared.u64 t, %1; cvt.u32.u64 %0, t; }"
        : "=r"(a) : "l"(p));
    return a;
}
static __device__ __forceinline__ ull pk2(float v) {
    ull r;
    unsigned b = __float_as_uint(v);
    asm("mov.b64 %0, {%1, %1};" : "=l"(r) : "r"(b));
    return r;
}
static __device__ __forceinline__ void ffma2(ull& a, ull x, ull w) {
    asm("fma.rn.f32x2 %0, %1, %2, %0;" : "+l"(a) : "l"(x), "l"(w));
}
static __device__ __forceinline__ float2 upk2(ull v) {
    unsigned lo, hi;
    asm("mov.b64 {%0, %1}, %2;" : "=r"(lo), "=r"(hi) : "l"(v));
    return make_float2(__uint_as_float(lo), __uint_as_float(hi));
}
static __device__ __forceinline__ void hsplit(float v, unsigned short& h,
                                              unsigned short& l) {
    __half hh = __float2half_rn(v);
    float hv = __half2float(hh);
    __half ll = __float2half_rn(v - hv);
    h = __half_as_ushort(hh);
    l = __half_as_ushort(ll);
}
static __device__ __forceinline__ void ldsm4(unsigned* r, unsigned addr) {
    asm volatile("ldmatrix.sync.aligned.m8n8.x4.shared.b16 {%0,%1,%2,%3}, [%4];"
                 : "=r"(r[0]), "=r"(r[1]), "=r"(r[2]), "=r"(r[3]) : "r"(addr));
}
static __device__ __forceinline__ void mma16816(float* d, const unsigned* a,
                                                const unsigned* b) {
    asm volatile(
        "mma.sync.aligned.m16n8k16.row.col.f32.f16.f16.f32 "
        "{%0,%1,%2,%3}, {%4,%5,%6,%7}, {%8,%9}, {%0,%1,%2,%3};"
        : "+f"(d[0]), "+f"(d[1]), "+f"(d[2]), "+f"(d[3])
        : "r"(a[0]), "r"(a[1]), "r"(a[2]), "r"(a[3]), "r"(b[0]), "r"(b[1]));
}
#define CP_ASYNC16(dst, src) \
    asm volatile("cp.async.cg.shared.global [%0], [%1], 16;" \
                 :: "r"(dst), "l"(src) : "memory")
#define CP_COMMIT() asm volatile("cp.async.commit_group;" ::: "memory")
#define CP_WAIT0()  asm volatile("cp.async.wait_group 0;" ::: "memory")

static __device__ __forceinline__ void prefetch_raw(unsigned sb, const float* y,
                                                    const float* x, long long pt0,
                                                    int tid) {
    const float4* ysrc = (const float4*)y + pt0 * 512;
    const float4* xsrc = (const float4*)x + pt0 * 32;
    for (int u = tid; u < 4352; u += THREADS) {
        unsigned dst = sb + OFF_RAW + (unsigned)u * 16;
        const float4* src = (u < 4096) ? (ysrc + u) : (xsrc + (u - 4096));
        CP_ASYNC16(dst, src);
    }
}

__global__ void __launch_bounds__(THREADS, 1)
ca_r15_kernel(const float* __restrict__ x,
              const float* __restrict__ y,
              const float* __restrict__ ln_g,
              const float* __restrict__ ln_b,
              const float* __restrict__ Wq,
              const float* __restrict__ Wkv,
              const float* __restrict__ Wo,
              const float* __restrict__ bo,
              float* __restrict__ out,
              int P)
{
    extern __shared__ float smf[];
    char* smb = (char*)smf;
    const unsigned sb = smem_u32(smf);

    const int tid  = threadIdx.x;
    const int warp = tid >> 5;
    const int lane = tid & 31;
    const int gid  = lane >> 2;
    const int tig  = lane & 3;
    const int jj   = tid & 127;
    const int qq   = tid >> 7;      // contraction quarter

    float* sXNT = (float*)(smb + OFF_XNT);
    float* sQ   = (float*)(smb + OFF_Q);
    float* sDOT = (float*)(smb + OFF_DOT);
    float* sTMP = (float*)(smb + OFF_TMP);
    float* sAOT = (float*)(smb + OFF_AOT);
    float* sG   = (float*)(smb + OFF_G);
    float* sB   = (float*)(smb + OFF_B);
    float* sBO  = (float*)(smb + OFF_BOV);

    if (tid < 128) { sG[tid] = ln_g[tid]; sB[tid] = ln_b[tid]; sBO[tid] = bo[tid]; }

    // ---- Wkv -> fp16 swizzled B tile [n=256][k=128] (once per CTA) ----
    for (int idx = tid; idx < 32768; idx += THREADS) {
        int k = idx >> 8, n = idx & 255;   // Wkv[k][n], coalesced read
        *(unsigned short*)(smb + OFF_BH + sw_off(n, k)) =
            __half_as_ushort(__float2half_rn(Wkv[idx]));
    }
    __syncthreads();

    // warp tiling: 2 m-halves x 8 n-tiles of 32
    const int mh    = warp >> 3;          // 0/1
    const int nn    = warp & 7;           // 0..7
    const bool is_k = (nn < 4);
    const int head  = is_k ? nn : (nn - 4);
    const int pbase = mh * 4;

    // ldmatrix per-lane addressing (loop-invariant parts)
    const int rowA  = mh * 64 + (lane & 15);
    const int kca   = lane >> 4;
    const int swa   = rowA & 7;
    const int nrowB = nn * 32 + (lane & 7) + ((lane >> 4) & 1) * 8;
    const int kcb   = (lane >> 3) & 1;
    const int swb   = nrowB & 7;
    const unsigned sbb = sb + OFF_BH + (unsigned)(nrowB * 256);
    const unsigned saH = sb + OFF_AH + (unsigned)(rowA * 256);
    const unsigned saL = sb + OFF_AL + (unsigned)(rowA * 256);

    const int nch = P >> 3;
    int c = blockIdx.x;
    if (c < nch) prefetch_raw(sb, y, x, (long long)c * 8, tid);
    CP_COMMIT();

    for (; c < nch; c += gridDim.x) {
        const long long pt0 = (long long)c * 8;
        CP_WAIT0();
        __syncthreads();

        // ============ LN + pack from raw SMEM (136 rows) ============
        for (int r = warp; r < 136; r += 16) {
            float4 v4 = ((const float4*)(smb + OFF_RAW))[r * 32 + lane];
            float s  = v4.x + v4.y + v4.z + v4.w;
            float q2 = v4.x * v4.x + v4.y * v4.y + v4.z * v4.z + v4.w * v4.w;
#pragma unroll
            for (int o = 16; o > 0; o >>= 1) {
                s  += __shfl_xor_sync(0xffffffffu, s,  o);
                q2 += __shfl_xor_sync(0xffffffffu, q2, o);
            }
            float mu  = s * (1.0f / 128.0f);
            float var = q2 * (1.0f / 128.0f) - mu * mu;
            float rs  = rsqrtf(var + 1e-5f);
            int k0 = lane * 4;
            float n0 = (v4.x - mu) * rs * sG[k0]     + sB[k0];
            float n1 = (v4.y - mu) * rs * sG[k0 + 1] + sB[k0 + 1];
            float n2 = (v4.z - mu) * rs * sG[k0 + 2] + sB[k0 + 2];
            float n3 = (v4.w - mu) * rs * sG[k0 + 3] + sB[k0 + 3];
            if (r < 128) {
                unsigned short h0, l0, h1, l1, h2, l2, h3, l3;
                hsplit(n0, h0, l0); hsplit(n1, h1, l1);
                hsplit(n2, h2, l2); hsplit(n3, h3, l3);
                int boff = r * 256 + ((((k0 >> 3) ^ (r & 7)) << 4)) + ((k0 & 7) << 1);
                *(uint2*)(smb + OFF_AH + boff) =
                    make_uint2((unsigned)h0 | ((unsigned)h1 << 16),
                               (unsigned)h2 | ((unsigned)h3 << 16));
                *(uint2*)(smb + OFF_AL + boff) =
                    make_uint2((unsigned)l0 | ((unsigned)l1 << 16),
                               (unsigned)l2 | ((unsigned)l3 << 16));
            } else {
                int p = r - 128;
                sXNT[(k0)     * 8 + p] = n0;
                sXNT[(k0 + 1) * 8 + p] = n1;
                sXNT[(k0 + 2) * 8 + p] = n2;
                sXNT[(k0 + 3) * 8 + p] = n3;
            }
        }
        __syncthreads();

        // ---- issue prefetch for next chunk (overlaps everything below) ----
        {
            long long cn = (long long)c + gridDim.x;
            if (cn < nch) prefetch_raw(sb, y, x, cn * 8, tid);
            CP_COMMIT();
        }

        // ============ q GEMM: 4-way contraction split ============
        {
            ull qa0 = 0, qa1 = 0, qa2 = 0, qa3 = 0;
            const float* xt  = sXNT + (qq * 32) * 8;
            const float* wqp = Wq + (qq * 32) * 128 + jj;
#pragma unroll 8
            for (int ii = 0; ii < 32; ++ii) {
                ulonglong2 xa = *(const ulonglong2*)(xt + ii * 8);
                ulonglong2 xb = *(const ulonglong2*)(xt + ii * 8 + 4);
                ull w = pk2(wqp[ii * 128]);
                ffma2(qa0, xa.x, w); ffma2(qa1, xa.y, w);
                ffma2(qa2, xb.x, w); ffma2(qa3, xb.y, w);
            }
            float2 f0 = upk2(qa0), f1 = upk2(qa1), f2 = upk2(qa2), f3 = upk2(qa3);
            float rr[8] = { f0.x, f0.y, f1.x, f1.y, f2.x, f2.y, f3.x, f3.y };
            if (qq) {
                float* tp = sTMP + (qq - 1) * 1024;
#pragma unroll
                for (int p = 0; p < 8; ++p) tp[p * 128 + jj] = rr[p];
            }
            __syncthreads();
            if (!qq) {
#pragma unroll
                for (int p = 0; p < 8; ++p)
                    sQ[p * 128 + jj] = rr[p] + sTMP[p * 128 + jj]
                                     + sTMP[1024 + p * 128 + jj]
                                     + sTMP[2048 + p * 128 + jj];
            }
            __syncthreads();   // sQ visible before dots
        }

        // ============ kv GEMM: 64m x 32n per warp, B hoisted per k-step ======
        float acc[4][4][4];
#pragma unroll
        for (int mt = 0; mt < 4; ++mt)
#pragma unroll
            for (int nt = 0; nt < 4; ++nt)
#pragma unroll
                for (int e = 0; e < 4; ++e) acc[mt][nt][e] = 0.0f;

#pragma unroll
        for (int ks = 0; ks < 8; ++ks) {
            unsigned bfr[2][4];
            unsigned bko = (unsigned)(((ks * 2 + kcb) ^ swb)) << 4;
            ldsm4(bfr[0], sbb + bko);
            ldsm4(bfr[1], sbb + 4096 + bko);
            unsigned ako = (unsigned)(((ks * 2 + kca) ^ swa)) << 4;
#pragma unroll
            for (int t = 0; t < 2; ++t) {
                const unsigned sa = t ? saL : saH;
#pragma unroll
                for (int mt = 0; mt < 4; ++mt) {
                    unsigned af[4];
                    ldsm4(af, sa + mt * 4096 + ako);
                    mma16816(acc[mt][0], af, &bfr[0][0]);
                    mma16816(acc[mt][1], af, &bfr[0][2]);
                    mma16816(acc[mt][2], af, &bfr[1][0]);
                    mma16816(acc[mt][3], af, &bfr[1][2]);
                }
            }
        }

        // ============ dots from k-fragments (warps with nn<4) ============
        if (is_k) {
#pragma unroll
            for (int mt = 0; mt < 4; ++mt) {
                int p = pbase + mt;
                float d0 = 0.0f, d1 = 0.0f;
#pragma unroll
                for (int nt = 0; nt < 4; ++nt) {
                    float2 qv = *(const float2*)(sQ + p * 128 + head * 32
                                                 + nt * 8 + tig * 2);
                    const float* cc = acc[mt][nt];
                    d0 += cc[0] * qv.x + cc[1] * qv.y;
                    d1 += cc[2] * qv.x + cc[3] * qv.y;
                }
#pragma unroll
                for (int o = 1; o < 4; o <<= 1) {
                    d0 += __shfl_xor_sync(0xffffffffu, d0, o);
                    d1 += __shfl_xor_sync(0xffffffffu, d1, o);
                }
                if (tig == 0) {
                    sDOT[(p * 4 + head) * 16 + gid]     = d0 * SCALE_F;
                    sDOT[(p * 4 + head) * 16 + gid + 8] = d1 * SCALE_F;
                }
            }
        }
        __syncthreads();

        // ============ softmax over m=16 (32 (p,h) rows) ============
        if (tid < 32) {
            float* dd = sDOT + tid * 16;
            float mx = dd[0];
#pragma unroll
            for (int m = 1; m < 16; ++m) mx = fmaxf(mx, dd[m]);
            float se = 0.0f;
            float ee[16];
#pragma unroll
            for (int m = 0; m < 16; ++m) { ee[m] = __expf(dd[m] - mx); se += ee[m]; }
            float inv = 1.0f / se;
#pragma unroll
            for (int m = 0; m < 16; ++m) dd[m] = ee[m] * inv;
        }
        __syncthreads();

        // ============ attn * v from v-fragments (warps with nn>=4) ==========
        if (!is_k) {
#pragma unroll
            for (int mt = 0; mt < 4; ++mt) {
                int p = pbase + mt;
                float ag  = sDOT[(p * 4 + head) * 16 + gid];
                float ag8 = sDOT[(p * 4 + head) * 16 + gid + 8];
#pragma unroll
                for (int nt = 0; nt < 4; ++nt) {
                    const float* cc = acc[mt][nt];
                    float o0 = ag * cc[0] + ag8 * cc[2];
                    float o1 = ag * cc[1] + ag8 * cc[3];
#pragma unroll
                    for (int o = 4; o < 32; o <<= 1) {
                        o0 += __shfl_xor_sync(0xffffffffu, o0, o);
                        o1 += __shfl_xor_sync(0xffffffffu, o1, o);
                    }
                    if (gid == 0) {
                        int d0 = nt * 8 + tig * 2;
                        sAOT[(head * 32 + d0) * 8 + p]     = o0;
                        sAOT[(head * 32 + d0 + 1) * 8 + p] = o1;
                    }
                }
            }
        }
        __syncthreads();

        // ============ out GEMM (4-way split) + bias + residual ============
        {
            ull oa0 = 0, oa1 = 0, oa2 = 0, oa3 = 0;
            const float* at  = sAOT + (qq * 32) * 8;
            const float* wop = Wo + (qq * 32) * 128 + jj;
#pragma unroll 8
            for (int ii = 0; ii < 32; ++ii) {
                ulonglong2 xa = *(const ulonglong2*)(at + ii * 8);
                ulonglong2 xb = *(const ulonglong2*)(at + ii * 8 + 4);
                ull w = pk2(wop[ii * 128]);
                ffma2(oa0, xa.x, w); ffma2(oa1, xa.y, w);
                ffma2(oa2, xb.x, w); ffma2(oa3, xb.y, w);
            }
            float2 f0 = upk2(oa0), f1 = upk2(oa1), f2 = upk2(oa2), f3 = upk2(oa3);
            float rr[8] = { f0.x, f0.y, f1.x, f1.y, f2.x, f2.y, f3.x, f3.y };
            if (qq) {
                float* tp = sTMP + (qq - 1) * 1024;
#pragma unroll
                for (int p = 0; p < 8; ++p) tp[p * 128 + jj] = rr[p];
            }
            __syncthreads();
            if (!qq) {
#pragma unroll
                for (int p = 0; p < 8; ++p) {
                    float v = rr[p] + sTMP[p * 128 + jj]
                            + sTMP[1024 + p * 128 + jj]
                            + sTMP[2048 + p * 128 + jj]
                            + sBO[jj] + x[(pt0 + p) * 128 + jj];
                    out[(pt0 + p) * 128 + jj] = v;
                }
            }
            __syncthreads();   // protect sTMP/sQ/sDOT/A tiles before next chunk
        }
    }
}

extern "C" void kernel_launch(void* const* d_in, const int* in_sizes, int n_in,
                              void* d_out, int out_size) {
    const float* x    = (const float*)d_in[0];
    const float* y    = (const float*)d_in[1];
    const float* ln_g = (const float*)d_in[2];
    const float* ln_b = (const float*)d_in[3];
    const float* Wq   = (const float*)d_in[4];
    const float* Wkv  = (const float*)d_in[5];
    const float* Wo   = (const float*)d_in[6];
    const float* bo   = (const float*)d_in[7];
    float* out = (float*)d_out;

    const int P = in_sizes[0] / 128;

    int dev = 0;
    cudaGetDevice(&dev);
    int sms = 0;
    cudaDeviceGetAttribute(&sms, cudaDevAttrMultiProcessorCount, dev);
    if (sms <= 0) sms = 148;

    cudaFuncSetAttribute(ca_r15_kernel,
                         cudaFuncAttributeMaxDynamicSharedMemorySize, SMEM_BYTES);

    ca_r15_kernel<<<sms, THREADS, SMEM_BYTES>>>(
        x, y, ln_g, ln_b, Wq, Wkv, Wo, bo, out, P);
}

// round 16
// speedup vs baseline: 1.4247x; 1.2316x over previous
#include <cuda_runtime.h>
#include <cuda_fp16.h>

// Fused PreNorm cross-attention, R16 = R15 with single-term fp16 MMA
// (A = fp16(yn), B = fp16(Wkv); quadrature error analysis + measured
// rel_err evidence shows 2-term split unnecessary at the 1e-3 gate).
// 512 threads / 16 warps, 1 CTA/SM persistent, 8 points per chunk.
// kv GEMM D[128m x 256n], warp tile 64m x 32n, epilogue from fragments,
// cp.async prefetch of raw y/x one chunk ahead.

#define THREADS 512
#define SCALE_F 0.17677669529663687f
typedef unsigned long long ull;

// ---- smem byte offsets ----
#define OFF_BH  0        // 65536 : Wkv fp16 [n=256][k=128], xor-swizzled
#define OFF_AH  65536    // 32768 : yn fp16 [m=128][k=128], xor-swizzled
#define OFF_RAW 98304    // 69632 : raw stage [136 rows][128 f32]
#define OFF_XNT 167936   // 4096  : xn transposed [i=128][p=8] fp32
#define OFF_Q   172032   // 4096  : q [p=8][128]
#define OFF_DOT 176128   // 2048  : dots/attn [(p*4+h)=32][m=16]
#define OFF_TMP 178176   // 12288 : 3 partial buffers [8][128] fp32
#define OFF_AOT 190464   // 4096  : attn-out transposed [i=128][p=8]
#define OFF_G   194560   // 512
#define OFF_B   195072   // 512
#define OFF_BOV 195584   // 512
#define SMEM_BYTES 196096

// xor-swizzled tile offset: row stride 256B (128 fp16), 16B chunks xor'd by row&7
static __device__ __forceinline__ int sw_off(int row, int k) {
    return row * 256 + ((((k >> 3) ^ (row & 7)) << 4)) + ((k & 7) << 1);
}
static __device__ __forceinline__ unsigned smem_u32(const void* p) {
    unsigned a;
    asm("{ .reg .u64 t; cvta.to.shared.u64 t, %1; cvt.u32.u64 %0, t; }"
        : "=r"(a) : "l"(p));
    return a;
}
static __device__ __forceinline__ ull pk2(float v) {
    ull r;
    unsigned b = __float_as_uint(v);
    asm("mov.b64 %0, {%1, %1};" : "=l"(r) : "r"(b));
    return r;
}
static __device__ __forceinline__ void ffma2(ull& a, ull x, ull w) {
    asm("fma.rn.f32x2 %0, %1, %2, %0;" : "+l"(a) : "l"(x), "l"(w));
}
static __device__ __forceinline__ float2 upk2(ull v) {
    unsigned lo, hi;
    asm("mov.b64 {%0, %1}, %2;" : "=r"(lo), "=r"(hi) : "l"(v));
    return make_float2(__uint_as_float(lo), __uint_as_float(hi));
}
static __device__ __forceinline__ void ldsm4(unsigned* r, unsigned addr) {
    asm volatile("ldmatrix.sync.aligned.m8n8.x4.shared.b16 {%0,%1,%2,%3}, [%4];"
                 : "=r"(r[0]), "=r"(r[1]), "=r"(r[2]), "=r"(r[3]) : "r"(addr));
}
static __device__ __forceinline__ void mma16816(float* d, const unsigned* a,
                                                const unsigned* b) {
    asm volatile(
        "mma.sync.aligned.m16n8k16.row.col.f32.f16.f16.f32 "
        "{%0,%1,%2,%3}, {%4,%5,%6,%7}, {%8,%9}, {%0,%1,%2,%3};"
        : "+f"(d[0]), "+f"(d[1]), "+f"(d[2]), "+f"(d[3])
        : "r"(a[0]), "r"(a[1]), "r"(a[2]), "r"(a[3]), "r"(b[0]), "r"(b[1]));
}
#define CP_ASYNC16(dst, src) \
    asm volatile("cp.async.cg.shared.global [%0], [%1], 16;" \
                 :: "r"(dst), "l"(src) : "memory")
#define CP_COMMIT() asm volatile("cp.async.commit_group;" ::: "memory")
#define CP_WAIT0()  asm volatile("cp.async.wait_group 0;" ::: "memory")

static __device__ __forceinline__ void prefetch_raw(unsigned sb, const float* y,
                                                    const float* x, long long pt0,
                                                    int tid) {
    const float4* ysrc = (const float4*)y + pt0 * 512;
    const float4* xsrc = (const float4*)x + pt0 * 32;
    for (int u = tid; u < 4352; u += THREADS) {
        unsigned dst = sb + OFF_RAW + (unsigned)u * 16;
        const float4* src = (u < 4096) ? (ysrc + u) : (xsrc + (u - 4096));
        CP_ASYNC16(dst, src);
    }
}

__global__ void __launch_bounds__(THREADS, 1)
ca_r16_kernel(const float* __restrict__ x,
              const float* __restrict__ y,
              const float* __restrict__ ln_g,
              const float* __restrict__ ln_b,
              const float* __restrict__ Wq,
              const float* __restrict__ Wkv,
              const float* __restrict__ Wo,
              const float* __restrict__ bo,
              float* __restrict__ out,
              int P)
{
    extern __shared__ float smf[];
    char* smb = (char*)smf;
    const unsigned sb = smem_u32(smf);

    const int tid  = threadIdx.x;
    const int warp = tid >> 5;
    const int lane = tid & 31;
    const int gid  = lane >> 2;
    const int tig  = lane & 3;
    const int jj   = tid & 127;
    const int qq   = tid >> 7;      // contraction quarter

    float* sXNT = (float*)(smb + OFF_XNT);
    float* sQ   = (float*)(smb + OFF_Q);
    float* sDOT = (float*)(smb + OFF_DOT);
    float* sTMP = (float*)(smb + OFF_TMP);
    float* sAOT = (float*)(smb + OFF_AOT);
    float* sG   = (float*)(smb + OFF_G);
    float* sB   = (float*)(smb + OFF_B);
    float* sBO  = (float*)(smb + OFF_BOV);

    if (tid < 128) { sG[tid] = ln_g[tid]; sB[tid] = ln_b[tid]; sBO[tid] = bo[tid]; }

    // ---- Wkv -> fp16 swizzled B tile [n=256][k=128] (once per CTA) ----
    for (int idx = tid; idx < 32768; idx += THREADS) {
        int k = idx >> 8, n = idx & 255;   // Wkv[k][n], coalesced read
        *(unsigned short*)(smb + OFF_BH + sw_off(n, k)) =
            __half_as_ushort(__float2half_rn(Wkv[idx]));
    }
    __syncthreads();

    // warp tiling: 2 m-halves x 8 n-tiles of 32
    const int mh    = warp >> 3;          // 0/1
    const int nn    = warp & 7;           // 0..7
    const bool is_k = (nn < 4);
    const int head  = is_k ? nn : (nn - 4);
    const int pbase = mh * 4;

    // ldmatrix per-lane addressing (loop-invariant parts)
    const int rowA  = mh * 64 + (lane & 15);
    const int kca   = lane >> 4;
    const int swa   = rowA & 7;
    const int nrowB = nn * 32 + (lane & 7) + ((lane >> 4) & 1) * 8;
    const int kcb   = (lane >> 3) & 1;
    const int swb   = nrowB & 7;
    const unsigned sbb = sb + OFF_BH + (unsigned)(nrowB * 256);
    const unsigned saH = sb + OFF_AH + (unsigned)(rowA * 256);

    const int nch = P >> 3;
    int c = blockIdx.x;
    if (c < nch) prefetch_raw(sb, y, x, (long long)c * 8, tid);
    CP_COMMIT();

    for (; c < nch; c += gridDim.x) {
        const long long pt0 = (long long)c * 8;
        CP_WAIT0();
        __syncthreads();

        // ============ LN + pack from raw SMEM (136 rows) ============
        for (int r = warp; r < 136; r += 16) {
            float4 v4 = ((const float4*)(smb + OFF_RAW))[r * 32 + lane];
            float s  = v4.x + v4.y + v4.z + v4.w;
            float q2 = v4.x * v4.x + v4.y * v4.y + v4.z * v4.z + v4.w * v4.w;
#pragma unroll
            for (int o = 16; o > 0; o >>= 1) {
                s  += __shfl_xor_sync(0xffffffffu, s,  o);
                q2 += __shfl_xor_sync(0xffffffffu, q2, o);
            }
            float mu  = s * (1.0f / 128.0f);
            float var = q2 * (1.0f / 128.0f) - mu * mu;
            float rs  = rsqrtf(var + 1e-5f);
            int k0 = lane * 4;
            float n0 = (v4.x - mu) * rs * sG[k0]     + sB[k0];
            float n1 = (v4.y - mu) * rs * sG[k0 + 1] + sB[k0 + 1];
            float n2 = (v4.z - mu) * rs * sG[k0 + 2] + sB[k0 + 2];
            float n3 = (v4.w - mu) * rs * sG[k0 + 3] + sB[k0 + 3];
            if (r < 128) {
                __half2 h01 = __floats2half2_rn(n0, n1);
                __half2 h23 = __floats2half2_rn(n2, n3);
                int boff = r * 256 + ((((k0 >> 3) ^ (r & 7)) << 4)) + ((k0 & 7) << 1);
                *(uint2*)(smb + OFF_AH + boff) =
                    make_uint2(*(unsigned*)&h01, *(unsigned*)&h23);
            } else {
                int p = r - 128;
                sXNT[(k0)     * 8 + p] = n0;
                sXNT[(k0 + 1) * 8 + p] = n1;
                sXNT[(k0 + 2) * 8 + p] = n2;
                sXNT[(k0 + 3) * 8 + p] = n3;
            }
        }
        __syncthreads();

        // ---- issue prefetch for next chunk (overlaps everything below) ----
        {
            long long cn = (long long)c + gridDim.x;
            if (cn < nch) prefetch_raw(sb, y, x, cn * 8, tid);
            CP_COMMIT();
        }

        // ============ q GEMM: 4-way contraction split ============
        {
            ull qa0 = 0, qa1 = 0, qa2 = 0, qa3 = 0;
            const float* xt  = sXNT + (qq * 32) * 8;
            const float* wqp = Wq + (qq * 32) * 128 + jj;
#pragma unroll 8
            for (int ii = 0; ii < 32; ++ii) {
                ulonglong2 xa = *(const ulonglong2*)(xt + ii * 8);
                ulonglong2 xb = *(const ulonglong2*)(xt + ii * 8 + 4);
                ull w = pk2(wqp[ii * 128]);
                ffma2(qa0, xa.x, w); ffma2(qa1, xa.y, w);
                ffma2(qa2, xb.x, w); ffma2(qa3, xb.y, w);
            }
            float2 f0 = upk2(qa0), f1 = upk2(qa1), f2 = upk2(qa2), f3 = upk2(qa3);
            float rr[8] = { f0.x, f0.y, f1.x, f1.y, f2.x, f2.y, f3.x, f3.y };
            if (qq) {
                float* tp = sTMP + (qq - 1) * 1024;
#pragma unroll
                for (int p = 0; p < 8; ++p) tp[p * 128 + jj] = rr[p];
            }
            __syncthreads();
            if (!qq) {
#pragma unroll
                for (int p = 0; p < 8; ++p)
                    sQ[p * 128 + jj] = rr[p] + sTMP[p * 128 + jj]
                                     + sTMP[1024 + p * 128 + jj]
                                     + sTMP[2048 + p * 128 + jj];
            }
            __syncthreads();   // sQ visible before dots
        }

        // ============ kv GEMM: 64m x 32n per warp, single fp16 term =========
        float acc[4][4][4];
#pragma unroll
        for (int mt = 0; mt < 4; ++mt)
#pragma unroll
            for (int nt = 0; nt < 4; ++nt)
#pragma unroll
                for (int e = 0; e < 4; ++e) acc[mt][nt][e] = 0.0f;

#pragma unroll
        for (int ks = 0; ks < 8; ++ks) {
            unsigned bfr[2][4];
            unsigned bko = (unsigned)(((ks * 2 + kcb) ^ swb)) << 4;
            ldsm4(bfr[0], sbb + bko);
            ldsm4(bfr[1], sbb + 4096 + bko);
            unsigned ako = (unsigned)(((ks * 2 + kca) ^ swa)) << 4;
#pragma unroll
            for (int mt = 0; mt < 4; ++mt) {
                unsigned af[4];
                ldsm4(af, saH + mt * 4096 + ako);
                mma16816(acc[mt][0], af, &bfr[0][0]);
                mma16816(acc[mt][1], af, &bfr[0][2]);
                mma16816(acc[mt][2], af, &bfr[1][0]);
                mma16816(acc[mt][3], af, &bfr[1][2]);
            }
        }

        // ============ dots from k-fragments (warps with nn<4) ============
        if (is_k) {
#pragma unroll
            for (int mt = 0; mt < 4; ++mt) {
                int p = pbase + mt;
                float d0 = 0.0f, d1 = 0.0f;
#pragma unroll
                for (int nt = 0; nt < 4; ++nt) {
                    float2 qv = *(const float2*)(sQ + p * 128 + head * 32
                                                 + nt * 8 + tig * 2);
                    const float* cc = acc[mt][nt];
                    d0 += cc[0] * qv.x + cc[1] * qv.y;
                    d1 += cc[2] * qv.x + cc[3] * qv.y;
                }
#pragma unroll
                for (int o = 1; o < 4; o <<= 1) {
                    d0 += __shfl_xor_sync(0xffffffffu, d0, o);
                    d1 += __shfl_xor_sync(0xffffffffu, d1, o);
                }
                if (tig == 0) {
                    sDOT[(p * 4 + head) * 16 + gid]     = d0 * SCALE_F;
                    sDOT[(p * 4 + head) * 16 + gid + 8] = d1 * SCALE_F;
                }
            }
        }
        __syncthreads();

        // ============ softmax over m=16 (32 (p,h) rows) ============
        if (tid < 32) {
            float* dd = sDOT + tid * 16;
            float mx = dd[0];
#pragma unroll
            for (int m = 1; m < 16; ++m) mx = fmaxf(mx, dd[m]);
            float se = 0.0f;
            float ee[16];
#pragma unroll
            for (int m = 0; m < 16; ++m) { ee[m] = __expf(dd[m] - mx); se += ee[m]; }
            float inv = 1.0f / se;
#pragma unroll
            for (int m = 0; m < 16; ++m) dd[m] = ee[m] * inv;
        }
        __syncthreads();

        // ============ attn * v from v-fragments (warps with nn>=4) ==========
        if (!is_k) {
#pragma unroll
            for (int mt = 0; mt < 4; ++mt) {
                int p = pbase + mt;
                float ag  = sDOT[(p * 4 + head) * 16 + gid];
                float ag8 = sDOT[(p * 4 + head) * 16 + gid + 8];
#pragma unroll
                for (int nt = 0; nt < 4; ++nt) {
                    const float* cc = acc[mt][nt];
                    float o0 = ag * cc[0] + ag8 * cc[2];
                    float o1 = ag * cc[1] + ag8 * cc[3];
#pragma unroll
                    for (int o = 4; o < 32; o <<= 1) {
                        o0 += __shfl_xor_sync(0xffffffffu, o0, o);
                        o1 += __shfl_xor_sync(0xffffffffu, o1, o);
                    }
                    if (gid == 0) {
                        int d0 = nt * 8 + tig * 2;
                        sAOT[(head * 32 + d0) * 8 + p]     = o0;
                        sAOT[(head * 32 + d0 + 1) * 8 + p] = o1;
                    }
                }
            }
        }
        __syncthreads();

        // ============ out GEMM (4-way split) + bias + residual ============
        {
            ull oa0 = 0, oa1 = 0, oa2 = 0, oa3 = 0;
            const float* at  = sAOT + (qq * 32) * 8;
            const float* wop = Wo + (qq * 32) * 128 + jj;
#pragma unroll 8
            for (int ii = 0; ii < 32; ++ii) {
                ulonglong2 xa = *(const ulonglong2*)(at + ii * 8);
                ulonglong2 xb = *(const ulonglong2*)(at + ii * 8 + 4);
                ull w = pk2(wop[ii * 128]);
                ffma2(oa0, xa.x, w); ffma2(oa1, xa.y, w);
                ffma2(oa2, xb.x, w); ffma2(oa3, xb.y, w);
            }
            float2 f0 = upk2(oa0), f1 = upk2(oa1), f2 = upk2(oa2), f3 = upk2(oa3);
            float rr[8] = { f0.x, f0.y, f1.x, f1.y, f2.x, f2.y, f3.x, f3.y };
            if (qq) {
                float* tp = sTMP + (qq - 1) * 1024;
#pragma unroll
                for (int p = 0; p < 8; ++p) tp[p * 128 + jj] = rr[p];
            }
            __syncthreads();
            if (!qq) {
#pragma unroll
                for (int p = 0; p < 8; ++p) {
                    float v = rr[p] + sTMP[p * 128 + jj]
                            + sTMP[1024 + p * 128 + jj]
                            + sTMP[2048 + p * 128 + jj]
                            + sBO[jj] + x[(pt0 + p) * 128 + jj];
                    out[(pt0 + p) * 128 + jj] = v;
                }
            }
            __syncthreads();   // protect sTMP/sQ/sDOT/A tiles before next chunk
        }
    }
}

extern "C" void kernel_launch(void* const* d_in, const int* in_sizes, int n_in,
                              void* d_out, int out_size) {
    const float* x    = (const float*)d_in[0];
    const float* y    = (const float*)d_in[1];
    const float* ln_g = (const float*)d_in[2];
    const float* ln_b = (const float*)d_in[3];
    const float* Wq   = (const float*)d_in[4];
    const float* Wkv  = (const float*)d_in[5];
    const float* Wo   = (const float*)d_in[6];
    const float* bo   = (const float*)d_in[7];
    float* out = (float*)d_out;

    const int P = in_sizes[0] / 128;

    int dev = 0;
    cudaGetDevice(&dev);
    int sms = 0;
    cudaDeviceGetAttribute(&sms, cudaDevAttrMultiProcessorCount, dev);
    if (sms <= 0) sms = 148;

    cudaFuncSetAttribute(ca_r16_kernel,
                         cudaFuncAttributeMaxDynamicSharedMemorySize, SMEM_BYTES);

    ca_r16_kernel<<<sms, THREADS, SMEM_BYTES>>>(
        x, y, ln_g, ln_b, Wq, Wkv, Wo, bo, out, P);
}

// round 17
// speedup vs baseline: 1.6865x; 1.1837x over previous
#include <cuda_runtime.h>
#include <cuda_fp16.h>

// Fused PreNorm cross-attention, R17 = R16 minus cp.async staging:
// LN loads y/x directly from global with batched LDG.128 (MLP ~9/warp),
// eliminating ~4350 cp.async ops (~8.7K LSU-issue cyc/chunk) and the
// SMEM round trip. Single-term fp16 HMMA (error-validated in R16).
// 512 threads / 16 warps, 1 CTA/SM persistent, 8 points per chunk.

#define THREADS 512
#define SCALE_F 0.17677669529663687f
typedef unsigned long long ull;

// ---- smem byte offsets ----
#define OFF_BH  0        // 65536 : Wkv fp16 [n=256][k=128], xor-swizzled
#define OFF_AH  65536    // 32768 : yn fp16 [m=128][k=128], xor-swizzled
#define OFF_XNT 98304    // 4096  : xn transposed [i=128][p=8] fp32
#define OFF_Q   102400   // 4096  : q [p=8][128]
#define OFF_DOT 106496   // 2048  : dots/attn [(p*4+h)=32][m=16]
#define OFF_TMP 108544   // 12288 : 3 partial buffers [8][128] fp32
#define OFF_AOT 120832   // 4096  : attn-out transposed [i=128][p=8]
#define OFF_G   124928   // 512
#define OFF_B   125440   // 512
#define OFF_BOV 125952   // 512
#define SMEM_BYTES 126464

// xor-swizzled tile offset: row stride 256B (128 fp16), 16B chunks xor'd by row&7
static __device__ __forceinline__ int sw_off(int row, int k) {
    return row * 256 + ((((k >> 3) ^ (row & 7)) << 4)) + ((k & 7) << 1);
}
static __device__ __forceinline__ unsigned smem_u32(const void* p) {
    unsigned a;
    asm("{ .reg .u64 t; cvta.to.shared.u64 t, %1; cvt.u32.u64 %0, t; }"
        : "=r"(a) : "l"(p));
    return a;
}
static __device__ __forceinline__ ull pk2(float v) {
    ull r;
    unsigned b = __float_as_uint(v);
    asm("mov.b64 %0, {%1, %1};" : "=l"(r) : "r"(b));
    return r;
}
static __device__ __forceinline__ void ffma2(ull& a, ull x, ull w) {
    asm("fma.rn.f32x2 %0, %1, %2, %0;" : "+l"(a) : "l"(x), "l"(w));
}
static __device__ __forceinline__ float2 upk2(ull v) {
    unsigned lo, hi;
    asm("mov.b64 {%0, %1}, %2;" : "=r"(lo), "=r"(hi) : "l"(v));
    return make_float2(__uint_as_float(lo), __uint_as_float(hi));
}
static __device__ __forceinline__ void ldsm4(unsigned* r, unsigned addr) {
    asm volatile("ldmatrix.sync.aligned.m8n8.x4.shared.b16 {%0,%1,%2,%3}, [%4];"
                 : "=r"(r[0]), "=r"(r[1]), "=r"(r[2]), "=r"(r[3]) : "r"(addr));
}
static __device__ __forceinline__ void mma16816(float* d, const unsigned* a,
                                                const unsigned* b) {
    asm volatile(
        "mma.sync.aligned.m16n8k16.row.col.f32.f16.f16.f32 "
        "{%0,%1,%2,%3}, {%4,%5,%6,%7}, {%8,%9}, {%0,%1,%2,%3};"
        : "+f"(d[0]), "+f"(d[1]), "+f"(d[2]), "+f"(d[3])
        : "r"(a[0]), "r"(a[1]), "r"(a[2]), "r"(a[3]), "r"(b[0]), "r"(b[1]));
}

__global__ void __launch_bounds__(THREADS, 1)
ca_r17_kernel(const float* __restrict__ x,
              const float* __restrict__ y,
              const float* __restrict__ ln_g,
              const float* __restrict__ ln_b,
              const float* __restrict__ Wq,
              const float* __restrict__ Wkv,
              const float* __restrict__ Wo,
              const float* __restrict__ bo,
              float* __restrict__ out,
              int P)
{
    extern __shared__ float smf[];
    char* smb = (char*)smf;
    const unsigned sb = smem_u32(smf);

    const int tid  = threadIdx.x;
    const int warp = tid >> 5;
    const int lane = tid & 31;
    const int gid  = lane >> 2;
    const int tig  = lane & 3;
    const int jj   = tid & 127;
    const int qq   = tid >> 7;      // contraction quarter

    float* sXNT = (float*)(smb + OFF_XNT);
    float* sQ   = (float*)(smb + OFF_Q);
    float* sDOT = (float*)(smb + OFF_DOT);
    float* sTMP = (float*)(smb + OFF_TMP);
    float* sAOT = (float*)(smb + OFF_AOT);
    float* sG   = (float*)(smb + OFF_G);
    float* sB   = (float*)(smb + OFF_B);
    float* sBO  = (float*)(smb + OFF_BOV);

    if (tid < 128) { sG[tid] = ln_g[tid]; sB[tid] = ln_b[tid]; sBO[tid] = bo[tid]; }

    // ---- Wkv -> fp16 swizzled B tile [n=256][k=128] (once per CTA) ----
    for (int idx = tid; idx < 32768; idx += THREADS) {
        int k = idx >> 8, n = idx & 255;   // Wkv[k][n], coalesced read
        *(unsigned short*)(smb + OFF_BH + sw_off(n, k)) =
            __half_as_ushort(__float2half_rn(Wkv[idx]));
    }
    __syncthreads();

    // warp tiling: 2 m-halves x 8 n-tiles of 32
    const int mh    = warp >> 3;          // 0/1
    const int nn    = warp & 7;           // 0..7
    const bool is_k = (nn < 4);
    const int head  = is_k ? nn : (nn - 4);
    const int pbase = mh * 4;

    // ldmatrix per-lane addressing (loop-invariant parts)
    const int rowA  = mh * 64 + (lane & 15);
    const int kca   = lane >> 4;
    const int swa   = rowA & 7;
    const int nrowB = nn * 32 + (lane & 7) + ((lane >> 4) & 1) * 8;
    const int kcb   = (lane >> 3) & 1;
    const int swb   = nrowB & 7;
    const unsigned sbb = sb + OFF_BH + (unsigned)(nrowB * 256);
    const unsigned saH = sb + OFF_AH + (unsigned)(rowA * 256);

    const int nch = P >> 3;
    for (int c = blockIdx.x; c < nch; c += gridDim.x) {
        const long long pt0 = (long long)c * 8;

        // ============ LN: batched direct LDG.128 (MLP ~9/warp), then pack ====
        {
            float4 v[9];
            // issue all loads first — overlap the DRAM latency
#pragma unroll
            for (int i = 0; i < 9; ++i) {
                int r = warp + i * 16;
                if (r < 128)       v[i] = ((const float4*)y)[(pt0 * 16 + r) * 32 + lane];
                else if (r < 136)  v[i] = ((const float4*)x)[(pt0 + (r - 128)) * 32 + lane];
            }
#pragma unroll
            for (int i = 0; i < 9; ++i) {
                int r = warp + i * 16;
                if (r >= 136) break;
                float4 v4 = v[i];
                float s  = v4.x + v4.y + v4.z + v4.w;
                float q2 = v4.x * v4.x + v4.y * v4.y + v4.z * v4.z + v4.w * v4.w;
#pragma unroll
                for (int o = 16; o > 0; o >>= 1) {
                    s  += __shfl_xor_sync(0xffffffffu, s,  o);
                    q2 += __shfl_xor_sync(0xffffffffu, q2, o);
                }
                float mu  = s * (1.0f / 128.0f);
                float var = q2 * (1.0f / 128.0f) - mu * mu;
                float rs  = rsqrtf(var + 1e-5f);
                int k0 = lane * 4;
                float n0 = (v4.x - mu) * rs * sG[k0]     + sB[k0];
                float n1 = (v4.y - mu) * rs * sG[k0 + 1] + sB[k0 + 1];
                float n2 = (v4.z - mu) * rs * sG[k0 + 2] + sB[k0 + 2];
                float n3 = (v4.w - mu) * rs * sG[k0 + 3] + sB[k0 + 3];
                if (r < 128) {
                    __half2 h01 = __floats2half2_rn(n0, n1);
                    __half2 h23 = __floats2half2_rn(n2, n3);
                    int boff = r * 256 + ((((k0 >> 3) ^ (r & 7)) << 4)) + ((k0 & 7) << 1);
                    *(uint2*)(smb + OFF_AH + boff) =
                        make_uint2(*(unsigned*)&h01, *(unsigned*)&h23);
                } else {
                    int p = r - 128;
                    sXNT[(k0)     * 8 + p] = n0;
                    sXNT[(k0 + 1) * 8 + p] = n1;
                    sXNT[(k0 + 2) * 8 + p] = n2;
                    sXNT[(k0 + 3) * 8 + p] = n3;
                }
            }
        }
        __syncthreads();

        // ============ q GEMM: 4-way contraction split ============
        {
            ull qa0 = 0, qa1 = 0, qa2 = 0, qa3 = 0;
            const float* xt  = sXNT + (qq * 32) * 8;
            const float* wqp = Wq + (qq * 32) * 128 + jj;
#pragma unroll 8
            for (int ii = 0; ii < 32; ++ii) {
                ulonglong2 xa = *(const ulonglong2*)(xt + ii * 8);
                ulonglong2 xb = *(const ulonglong2*)(xt + ii * 8 + 4);
                ull w = pk2(wqp[ii * 128]);
                ffma2(qa0, xa.x, w); ffma2(qa1, xa.y, w);
                ffma2(qa2, xb.x, w); ffma2(qa3, xb.y, w);
            }
            float2 f0 = upk2(qa0), f1 = upk2(qa1), f2 = upk2(qa2), f3 = upk2(qa3);
            float rr[8] = { f0.x, f0.y, f1.x, f1.y, f2.x, f2.y, f3.x, f3.y };
            if (qq) {
                float* tp = sTMP + (qq - 1) * 1024;
#pragma unroll
                for (int p = 0; p < 8; ++p) tp[p * 128 + jj] = rr[p];
            }
            __syncthreads();
            if (!qq) {
#pragma unroll
                for (int p = 0; p < 8; ++p)
                    sQ[p * 128 + jj] = rr[p] + sTMP[p * 128 + jj]
                                     + sTMP[1024 + p * 128 + jj]
                                     + sTMP[2048 + p * 128 + jj];
            }
            __syncthreads();   // sQ visible before dots
        }

        // ============ kv GEMM: 64m x 32n per warp, single fp16 term =========
        float acc[4][4][4];
#pragma unroll
        for (int mt = 0; mt < 4; ++mt)
#pragma unroll
            for (int nt = 0; nt < 4; ++nt)
#pragma unroll
                for (int e = 0; e < 4; ++e) acc[mt][nt][e] = 0.0f;

#pragma unroll
        for (int ks = 0; ks < 8; ++ks) {
            unsigned bfr[2][4];
            unsigned bko = (unsigned)(((ks * 2 + kcb) ^ swb)) << 4;
            ldsm4(bfr[0], sbb + bko);
            ldsm4(bfr[1], sbb + 4096 + bko);
            unsigned ako = (unsigned)(((ks * 2 + kca) ^ swa)) << 4;
#pragma unroll
            for (int mt = 0; mt < 4; ++mt) {
                unsigned af[4];
                ldsm4(af, saH + mt * 4096 + ako);
                mma16816(acc[mt][0], af, &bfr[0][0]);
                mma16816(acc[mt][1], af, &bfr[0][2]);
                mma16816(acc[mt][2], af, &bfr[1][0]);
                mma16816(acc[mt][3], af, &bfr[1][2]);
            }
        }

        // ============ dots from k-fragments (warps with nn<4) ============
        if (is_k) {
#pragma unroll
            for (int mt = 0; mt < 4; ++mt) {
                int p = pbase + mt;
                float d0 = 0.0f, d1 = 0.0f;
#pragma unroll
                for (int nt = 0; nt < 4; ++nt) {
                    float2 qv = *(const float2*)(sQ + p * 128 + head * 32
                                                 + nt * 8 + tig * 2);
                    const float* cc = acc[mt][nt];
                    d0 += cc[0] * qv.x + cc[1] * qv.y;
                    d1 += cc[2] * qv.x + cc[3] * qv.y;
                }
#pragma unroll
                for (int o = 1; o < 4; o <<= 1) {
                    d0 += __shfl_xor_sync(0xffffffffu, d0, o);
                    d1 += __shfl_xor_sync(0xffffffffu, d1, o);
                }
                if (tig == 0) {
                    sDOT[(p * 4 + head) * 16 + gid]     = d0 * SCALE_F;
                    sDOT[(p * 4 + head) * 16 + gid + 8] = d1 * SCALE_F;
                }
            }
        }
        __syncthreads();

        // ============ softmax over m=16 (32 (p,h) rows) ============
        if (tid < 32) {
            float* dd = sDOT + tid * 16;
            float mx = dd[0];
#pragma unroll
            for (int m = 1; m < 16; ++m) mx = fmaxf(mx, dd[m]);
            float se = 0.0f;
            float ee[16];
#pragma unroll
            for (int m = 0; m < 16; ++m) { ee[m] = __expf(dd[m] - mx); se += ee[m]; }
            float inv = 1.0f / se;
#pragma unroll
            for (int m = 0; m < 16; ++m) dd[m] = ee[m] * inv;
        }
        __syncthreads();

        // ============ attn * v from v-fragments (warps with nn>=4) ==========
        if (!is_k) {
#pragma unroll
            for (int mt = 0; mt < 4; ++mt) {
                int p = pbase + mt;
                float ag  = sDOT[(p * 4 + head) * 16 + gid];
                float ag8 = sDOT[(p * 4 + head) * 16 + gid + 8];
#pragma unroll
                for (int nt = 0; nt < 4; ++nt) {
                    const float* cc = acc[mt][nt];
                    float o0 = ag * cc[0] + ag8 * cc[2];
                    float o1 = ag * cc[1] + ag8 * cc[3];
#pragma unroll
                    for (int o = 4; o < 32; o <<= 1) {
                        o0 += __shfl_xor_sync(0xffffffffu, o0, o);
                        o1 += __shfl_xor_sync(0xffffffffu, o1, o);
                    }
                    if (gid == 0) {
                        int d0 = nt * 8 + tig * 2;
                        sAOT[(head * 32 + d0) * 8 + p]     = o0;
                        sAOT[(head * 32 + d0 + 1) * 8 + p] = o1;
                    }
                }
            }
        }
        __syncthreads();

        // ============ out GEMM (4-way split) + bias + residual ============
        {
            ull oa0 = 0, oa1 = 0, oa2 = 0, oa3 = 0;
            const float* at  = sAOT + (qq * 32) * 8;
            const float* wop = Wo + (qq * 32) * 128 + jj;
#pragma unroll 8
            for (int ii = 0; ii < 32; ++ii) {
                ulonglong2 xa = *(const ulonglong2*)(at + ii * 8);
                ulonglong2 xb = *(const ulonglong2*)(at + ii * 8 + 4);
                ull w = pk2(wop[ii * 128]);
                ffma2(oa0, xa.x, w); ffma2(oa1, xa.y, w);
                ffma2(oa2, xb.x, w); ffma2(oa3, xb.y, w);
            }
            float2 f0 = upk2(oa0), f1 = upk2(oa1), f2 = upk2(oa2), f3 = upk2(oa3);
            float rr[8] = { f0.x, f0.y, f1.x, f1.y, f2.x, f2.y, f3.x, f3.y };
            if (qq) {
                float* tp = sTMP + (qq - 1) * 1024;
#pragma unroll
                for (int p = 0; p < 8; ++p) tp[p * 128 + jj] = rr[p];
            }
            __syncthreads();
            if (!qq) {
#pragma unroll
                for (int p = 0; p < 8; ++p) {
                    float v = rr[p] + sTMP[p * 128 + jj]
                            + sTMP[1024 + p * 128 + jj]
                            + sTMP[2048 + p * 128 + jj]
                            + sBO[jj] + x[(pt0 + p) * 128 + jj];
                    out[(pt0 + p) * 128 + jj] = v;
                }
            }
            __syncthreads();   // protect sTMP/sQ/sDOT/A tiles before next chunk
        }
    }
}

extern "C" void kernel_launch(void* const* d_in, const int* in_sizes, int n_in,
                              void* d_out, int out_size) {
    const float* x    = (const float*)d_in[0];
    const float* y    = (const float*)d_in[1];
    const float* ln_g = (const float*)d_in[2];
    const float* ln_b = (const float*)d_in[3];
    const float* Wq   = (const float*)d_in[4];
    const float* Wkv  = (const float*)d_in[5];
    const float* Wo   = (const float*)d_in[6];
    const float* bo   = (const float*)d_in[7];
    float* out = (float*)d_out;

    const int P = in_sizes[0] / 128;

    int dev = 0;
    cudaGetDevice(&dev);
    int sms = 0;
    cudaDeviceGetAttribute(&sms, cudaDevAttrMultiProcessorCount, dev);
    if (sms <= 0) sms = 148;

    cudaFuncSetAttribute(ca_r17_kernel,
                         cudaFuncAttributeMaxDynamicSharedMemorySize, SMEM_BYTES);

    ca_r17_kernel<<<sms, THREADS, SMEM_BYTES>>>(
        x, y, ln_g, ln_b, Wq, Wkv, Wo, bo, out, P);
}